// round 1
// baseline (speedup 1.0000x reference)
#include <cuda_runtime.h>
#include <math.h>

#define S 128
#define NRBF 20
#define DEG 16
#define MAXN 10240
#define BN 16
#define NODES_PER_BLK 8
#define NCHUNK 10

__device__ float g_phi[3 * S];
__device__ float g_state1[MAXN * S];
__device__ float g_vsum[MAXN * S];
__device__ float g_statef[MAXN * S];
__device__ float g_partial[256 * NCHUNK * S];

__device__ __forceinline__ float siluf(float x) {
    return x / (1.0f + expf(-x));
}

// ---------------------------------------------------------------------------
// Kernel 0: phi vector (single 384-vector since initial state is uniform)
// ---------------------------------------------------------------------------
__global__ void k_phi(const float* __restrict__ emb0,
                      const float* __restrict__ w1, const float* __restrict__ b1,
                      const float* __restrict__ w2, const float* __restrict__ b2) {
    __shared__ float h1[S];
    int t = threadIdx.x;
    if (t < S) {
        float acc = b1[t];
        for (int s = 0; s < S; s++)
            acc += (128.0f * emb0[s]) * w1[s * S + t];
        h1[t] = siluf(acc);
    }
    __syncthreads();
    if (t < 3 * S) {
        float acc = b2[t];
        for (int j = 0; j < S; j++)
            acc += h1[j] * w2[j * 3 * S + t];
        g_phi[t] = acc;
    }
}

// ---------------------------------------------------------------------------
// Kernel 1: per-node edge reduction -> rbf sufficient statistics ->
//           state1[n,s] and vsum[n,s].
// One half-warp (16 lanes) per node for the 16 contiguous edges.
// ---------------------------------------------------------------------------
__global__ void k_edge(const float* __restrict__ diffs,
                       const float* __restrict__ lens,
                       const float* __restrict__ filt_w,
                       const float* __restrict__ filt_b, int N) {
    __shared__ float sA[NODES_PER_BLK][NRBF];
    __shared__ float sB[NODES_PER_BLK][NRBF][3];
    __shared__ float sAb[NODES_PER_BLK];
    __shared__ float sBb[NODES_PER_BLK][3];
    __shared__ float sInv[NODES_PER_BLK];

    int tid = threadIdx.x;
    int g = tid >> 4;
    int le = tid & 15;
    int n = blockIdx.x * NODES_PER_BLK + g;
    int nc = min(n, N - 1);  // clamp so shfl stays uniform

    {
        int e = nc * DEG + le;
        float dx = diffs[e * 3 + 0];
        float dy = diffs[e * 3 + 1];
        float dz = diffs[e * 3 + 2];
        float len = lens[e];
        float r2 = dx * dx + dy * dy + dz * dz;
        float r = sqrtf(r2);
        float mask = (fabsf(len) <= 10.0f) ? 1.0f : 0.0f;
        float rsafe = fmaxf(r, 1e-12f);
        float inv_rs = 1.0f / rsafe;
        float cut = (r < 10.0f) ? 0.5f * (cospif(r * 0.1f) + 1.0f) : 0.0f;
        float pre = mask * cut;

        // frobenius norm of masked edge set
        float fr = mask * r2;
        #pragma unroll
        for (int m = 8; m; m >>= 1) fr += __shfl_xor_sync(0xffffffffu, fr, m, 16);
        float frob = sqrtf(fr);
        float den = (frob > 0.0f) ? frob : 1.0f;
        if (le == 0) sInv[g] = 1.0f / den;

        // bias-channel sums
        float t0 = pre, t1 = pre * dx, t2 = pre * dy, t3 = pre * dz;
        #pragma unroll
        for (int m = 8; m; m >>= 1) {
            t0 += __shfl_xor_sync(0xffffffffu, t0, m, 16);
            t1 += __shfl_xor_sync(0xffffffffu, t1, m, 16);
            t2 += __shfl_xor_sync(0xffffffffu, t2, m, 16);
            t3 += __shfl_xor_sync(0xffffffffu, t3, m, 16);
        }
        if (le == 0) { sAb[g] = t0; sBb[g][0] = t1; sBb[g][1] = t2; sBb[g][2] = t3; }

        float base = rsafe * 0.1f;
        for (int k = 0; k < NRBF; k++) {
            float rbf = sinpif((float)(k + 1) * base) * inv_rs;
            float q0 = pre * rbf;
            float q1 = q0 * dx, q2 = q0 * dy, q3 = q0 * dz;
            #pragma unroll
            for (int m = 8; m; m >>= 1) {
                q0 += __shfl_xor_sync(0xffffffffu, q0, m, 16);
                q1 += __shfl_xor_sync(0xffffffffu, q1, m, 16);
                q2 += __shfl_xor_sync(0xffffffffu, q2, m, 16);
                q3 += __shfl_xor_sync(0xffffffffu, q3, m, 16);
            }
            if (le == 0) {
                sA[g][k] = q0;
                sB[g][k][0] = q1; sB[g][k][1] = q2; sB[g][k][2] = q3;
            }
        }
    }
    __syncthreads();

    // Phase 2: per (node, s) 20-deep dot products against filt_w columns
    int s = tid;  // 0..127
    float phi2 = g_phi[S + s];
    float phi3 = g_phi[2 * S + s];
    float fb2 = filt_b[S + s];
    float fb3 = filt_b[2 * S + s];
    int c = s % 3;
    for (int ni = 0; ni < NODES_PER_BLK; ni++) {
        int nn = blockIdx.x * NODES_PER_BLK + ni;
        if (nn >= N) break;
        float ws2 = sAb[ni] * fb2;
        float wv = sBb[ni][c] * fb3;
        #pragma unroll
        for (int k = 0; k < NRBF; k++) {
            ws2 += sA[ni][k] * filt_w[k * 3 * S + S + s];
            wv  += sB[ni][k][c] * filt_w[k * 3 * S + 2 * S + s];
        }
        g_state1[nn * S + s] = phi2 * ws2;
        g_vsum[nn * S + s] = phi3 * wv * sInv[ni];
    }
}

// ---------------------------------------------------------------------------
// Kernel 2: fused per-node MLP (U,V, c=U.V, Vnorm, update MLP, final state),
// BN=16 nodes per block, 128 threads (thread t = feature column).
// ---------------------------------------------------------------------------
__global__ void __launch_bounds__(128) k_node(
        const float* __restrict__ u_w, const float* __restrict__ v_w,
        const float* __restrict__ w1, const float* __restrict__ b1,
        const float* __restrict__ w2, const float* __restrict__ b2, int N) {
    __shared__ float sv[BN][S];
    __shared__ float ss[BN][S];
    __shared__ float sU[BN][S];
    __shared__ float sV[BN][S];
    __shared__ float scp[4][BN];
    __shared__ float sc[BN];

    int t = threadIdx.x;
    int n0 = blockIdx.x * BN;

    for (int ni = 0; ni < BN; ni++) {
        int nn = min(n0 + ni, N - 1);
        sv[ni][t] = g_vsum[nn * S + t];
        ss[ni][t] = g_state1[nn * S + t];
    }
    __syncthreads();

    // uvec = vsum @ u_w, vvec = vsum @ v_w
    {
        float aU[BN], aV[BN];
        #pragma unroll
        for (int ni = 0; ni < BN; ni++) { aU[ni] = 0.0f; aV[ni] = 0.0f; }
        for (int s = 0; s < S; s++) {
            float wu = u_w[s * S + t];
            float wv = v_w[s * S + t];
            #pragma unroll
            for (int ni = 0; ni < BN; ni++) {
                float x = sv[ni][s];
                aU[ni] += x * wu;
                aV[ni] += x * wv;
            }
        }
        #pragma unroll
        for (int ni = 0; ni < BN; ni++) { sU[ni][t] = aU[ni]; sV[ni][t] = aV[ni]; }
    }
    __syncthreads();

    // c[n] = uvec . vvec (block reduction), and Vnorm = sqrt(3)*|vvec| into sv
    int warp = t >> 5, lane = t & 31;
    for (int ni = 0; ni < BN; ni++) {
        float v = sU[ni][t] * sV[ni][t];
        #pragma unroll
        for (int m = 16; m; m >>= 1) v += __shfl_xor_sync(0xffffffffu, v, m);
        if (lane == 0) scp[warp][ni] = v;
    }
    const float SQ3 = 1.7320508075688772f;
    #pragma unroll
    for (int ni = 0; ni < BN; ni++) sv[ni][t] = SQ3 * fabsf(sV[ni][t]);
    __syncthreads();
    if (t < BN) sc[t] = scp[0][t] + scp[1][t] + scp[2][t] + scp[3][t];
    __syncthreads();

    // h = silu([Vnorm, state1] @ upd_w1 + b1)   (write into sU, no longer needed)
    {
        float acc[BN];
        #pragma unroll
        for (int ni = 0; ni < BN; ni++) acc[ni] = 0.0f;
        for (int s = 0; s < S; s++) {
            float w = w1[s * S + t];
            #pragma unroll
            for (int ni = 0; ni < BN; ni++) acc[ni] += sv[ni][s] * w;
        }
        for (int s = 0; s < S; s++) {
            float w = w1[(S + s) * S + t];
            #pragma unroll
            for (int ni = 0; ni < BN; ni++) acc[ni] += ss[ni][s] * w;
        }
        float bb = b1[t];
        #pragma unroll
        for (int ni = 0; ni < BN; ni++) {
            float h = acc[ni] + bb;
            sU[ni][t] = siluf(h);
        }
    }
    __syncthreads();

    // a_sv, a_ss = h @ upd_w2 slices; final state = a_ss + 3c * a_sv
    {
        float asv[BN], ass[BN];
        #pragma unroll
        for (int ni = 0; ni < BN; ni++) { asv[ni] = 0.0f; ass[ni] = 0.0f; }
        for (int s = 0; s < S; s++) {
            float wsv = w2[s * 3 * S + S + t];
            float wss = w2[s * 3 * S + 2 * S + t];
            #pragma unroll
            for (int ni = 0; ni < BN; ni++) {
                float h = sU[ni][s];
                asv[ni] += h * wsv;
                ass[ni] += h * wss;
            }
        }
        float bsv = b2[S + t];
        float bss = b2[2 * S + t];
        for (int ni = 0; ni < BN; ni++) {
            int nn = n0 + ni;
            if (nn < N)
                g_statef[nn * S + t] =
                    (ass[ni] + bss) + 3.0f * sc[ni] * (asv[ni] + bsv);
        }
    }
}

// ---------------------------------------------------------------------------
// Kernel 3: deterministic chunked graph segment-sum
// ---------------------------------------------------------------------------
__global__ void k_graphpart(const int* __restrict__ gidx, int N, int chunk_sz) {
    int g = blockIdx.x, ch = blockIdx.y, t = threadIdx.x;
    int n0 = ch * chunk_sz;
    int n1 = min(n0 + chunk_sz, N);
    float acc = 0.0f;
    for (int n = n0; n < n1; n++) {
        if (gidx[n] == g) acc += g_statef[n * S + t];
    }
    g_partial[(g * gridDim.y + ch) * S + t] = acc;
}

// ---------------------------------------------------------------------------
// Kernel 4: combine chunks + output MLP per graph
// ---------------------------------------------------------------------------
__global__ void k_out(const float* __restrict__ w1, const float* __restrict__ b1,
                      const float* __restrict__ w2, const float* __restrict__ b2,
                      float* __restrict__ out, int nchunk) {
    __shared__ float gs[S];
    __shared__ float red[4];
    int g = blockIdx.x, t = threadIdx.x;
    float acc = 0.0f;
    for (int ch = 0; ch < nchunk; ch++)
        acc += g_partial[(g * nchunk + ch) * S + t];
    gs[t] = acc;
    __syncthreads();
    float hacc = b1[t];
    for (int s = 0; s < S; s++) hacc += gs[s] * w1[s * S + t];
    float h = siluf(hacc);
    float p = h * w2[t];
    #pragma unroll
    for (int m = 16; m; m >>= 1) p += __shfl_xor_sync(0xffffffffu, p, m);
    int warp = t >> 5, lane = t & 31;
    if (lane == 0) red[warp] = p;
    __syncthreads();
    if (t == 0) out[g] = red[0] + red[1] + red[2] + red[3] + b2[0];
}

// ---------------------------------------------------------------------------
extern "C" void kernel_launch(void* const* d_in, const int* in_sizes, int n_in,
                              void* d_out, int out_size) {
    int N = in_sizes[3];                 // node_graph_index
    int off = (n_in >= 22) ? 1 : 0;      // num_graphs scalar present?

    const float* diffs   = (const float*)d_in[0];
    const float* lens    = (const float*)d_in[1];
    const int*   gidx    = (const int*)d_in[3];
    const float* emb0    = (const float*)d_in[4 + off];
    const float* phi_w1  = (const float*)d_in[5 + off];
    const float* phi_b1  = (const float*)d_in[6 + off];
    const float* phi_w2  = (const float*)d_in[7 + off];
    const float* phi_b2  = (const float*)d_in[8 + off];
    const float* filt_w  = (const float*)d_in[9 + off];
    const float* filt_b  = (const float*)d_in[10 + off];
    const float* u_w     = (const float*)d_in[11 + off];
    const float* v_w     = (const float*)d_in[12 + off];
    const float* upd_w1  = (const float*)d_in[13 + off];
    const float* upd_b1  = (const float*)d_in[14 + off];
    const float* upd_w2  = (const float*)d_in[15 + off];
    const float* upd_b2  = (const float*)d_in[16 + off];
    const float* out_w1  = (const float*)d_in[17 + off];
    const float* out_b1  = (const float*)d_in[18 + off];
    const float* out_w2  = (const float*)d_in[19 + off];
    const float* out_b2  = (const float*)d_in[20 + off];
    float* out = (float*)d_out;
    int G = out_size;

    k_phi<<<1, 3 * S>>>(emb0, phi_w1, phi_b1, phi_w2, phi_b2);

    int nblk1 = (N + NODES_PER_BLK - 1) / NODES_PER_BLK;
    k_edge<<<nblk1, 128>>>(diffs, lens, filt_w, filt_b, N);

    int nblk2 = (N + BN - 1) / BN;
    k_node<<<nblk2, 128>>>(u_w, v_w, upd_w1, upd_b1, upd_w2, upd_b2, N);

    int csz = (N + NCHUNK - 1) / NCHUNK;
    dim3 g3(G, NCHUNK);
    k_graphpart<<<g3, 128>>>(gidx, N, csz);

    k_out<<<G, 128>>>(out_w1, out_b1, out_w2, out_b2, out, NCHUNK);
}

// round 2
// speedup vs baseline: 1.2983x; 1.2983x over previous
#include <cuda_runtime.h>
#include <math.h>

#define S 128
#define NRBF 20
#define DEG 16
#define MAXN 10240
#define BN 16
#define NPB 8          // nodes per block in k_edge
#define GMAX 64
#define GP_BLOCKS 128

__device__ float g_phi[3 * S];
__device__ float g_state1[MAXN * S];
__device__ float g_vsum[MAXN * S];
__device__ float g_statef[MAXN * S];
__device__ float g_partial[GP_BLOCKS * GMAX * S];

typedef unsigned long long ull;

__device__ __forceinline__ float siluf(float x) {
    return x / (1.0f + __expf(-x));
}
__device__ __forceinline__ ull pack2(float a, float b) {
    ull r;
    asm("mov.b64 %0, {%1,%2};" : "=l"(r) : "f"(a), "f"(b));
    return r;
}
__device__ __forceinline__ ull ffma2(ull a, ull b, ull c) {
    ull d;
    asm("fma.rn.f32x2 %0, %1, %2, %3;" : "=l"(d) : "l"(a), "l"(b), "l"(c));
    return d;
}
__device__ __forceinline__ void unpack2(ull p, float& lo, float& hi) {
    asm("mov.b64 {%0,%1}, %2;" : "=f"(lo), "=f"(hi) : "l"(p));
}

union U4 { float4 v; ull p[2]; };

// ---------------------------------------------------------------------------
// Kernel 0: phi vector (single 384-vector since initial state is uniform)
// ---------------------------------------------------------------------------
__global__ void k_phi(const float* __restrict__ emb0,
                      const float* __restrict__ w1, const float* __restrict__ b1,
                      const float* __restrict__ w2, const float* __restrict__ b2) {
    __shared__ float h1[S];
    int t = threadIdx.x;
    if (t < S) {
        float acc = b1[t];
        #pragma unroll 4
        for (int s = 0; s < S; s++)
            acc += (128.0f * emb0[s]) * w1[s * S + t];
        // reference silu here: keep accurate expf for the single vector
        h1[t] = acc / (1.0f + expf(-acc));
    }
    __syncthreads();
    if (t < 3 * S) {
        float acc = b2[t];
        #pragma unroll 4
        for (int j = 0; j < S; j++)
            acc += h1[j] * w2[j * 3 * S + t];
        g_phi[t] = acc;
    }
}

// ---------------------------------------------------------------------------
// Kernel 1: per-node edge reduction -> rbf sufficient statistics ->
//           state1[n,s] and vsum[n,s].
// 16 lanes per node. Sine recurrence + channel-interleaved butterfly reduce.
// ---------------------------------------------------------------------------
__global__ void __launch_bounds__(128) k_edge(
        const float* __restrict__ diffs,
        const float* __restrict__ lens,
        const float* __restrict__ filt_w,
        const float* __restrict__ filt_b, int N) {
    __shared__ __align__(16) float sA[NPB][NRBF];
    __shared__ __align__(16) float sB[NPB][3][NRBF];
    __shared__ float sAb[NPB];
    __shared__ float sBb[NPB][3];
    __shared__ float sInv[NPB];

    const unsigned FULL = 0xffffffffu;
    int tid = threadIdx.x;
    int g = tid >> 4;
    int le = tid & 15;
    int n = blockIdx.x * NPB + g;
    int nc = min(n, N - 1);   // clamp so shfl stays uniform

    {
        int e = nc * DEG + le;
        float dx = diffs[e * 3 + 0];
        float dy = diffs[e * 3 + 1];
        float dz = diffs[e * 3 + 2];
        float len = lens[e];
        float r2 = dx * dx + dy * dy + dz * dz;
        float r = sqrtf(r2);
        float mask = (fabsf(len) <= 10.0f) ? 1.0f : 0.0f;
        float rsafe = fmaxf(r, 1e-12f);
        float inv_rs = 1.0f / rsafe;
        float base = rsafe * 0.1f;
        float c1 = cospif(base);
        float s1 = sinpif(base);
        float cut = (r < 10.0f) ? 0.5f * (c1 + 1.0f) : 0.0f;
        float pre = mask * cut;
        float pir = pre * inv_rs;

        // frobenius of masked edge set
        float fr = mask * r2;
        #pragma unroll
        for (int m = 8; m; m >>= 1) fr += __shfl_xor_sync(FULL, fr, m);
        float frob = sqrtf(fr);
        float den = (frob > 0.0f) ? frob : 1.0f;
        if (le == 0) sInv[g] = 1.0f / den;

        // bias-channel sums via channel-interleaved butterfly
        {
            float q0 = pre, q1 = pre * dx, q2 = pre * dy, q3 = pre * dz;
            float a = (le & 1) ? q1 : q0;
            float b = (le & 1) ? q0 : q1;
            a += __shfl_xor_sync(FULL, b, 1);
            float c = (le & 1) ? q3 : q2;
            float d = (le & 1) ? q2 : q3;
            c += __shfl_xor_sync(FULL, d, 1);
            float e_ = (le & 2) ? c : a;
            float f_ = (le & 2) ? a : c;
            e_ += __shfl_xor_sync(FULL, f_, 2);
            e_ += __shfl_xor_sync(FULL, e_, 4);
            e_ += __shfl_xor_sync(FULL, e_, 8);
            if (le == 0) sAb[g] = e_;
            else if (le < 4) sBb[g][le - 1] = e_;
        }

        // rbf sums: sin((k+1)*pi*base) via recurrence
        float sk = s1, skm1 = 0.0f, c2 = 2.0f * c1;
        #pragma unroll
        for (int k = 0; k < NRBF; k++) {
            float q0 = pir * sk;
            float q1 = q0 * dx, q2 = q0 * dy, q3 = q0 * dz;
            float a = (le & 1) ? q1 : q0;
            float b = (le & 1) ? q0 : q1;
            a += __shfl_xor_sync(FULL, b, 1);
            float c = (le & 1) ? q3 : q2;
            float d = (le & 1) ? q2 : q3;
            c += __shfl_xor_sync(FULL, d, 1);
            float e_ = (le & 2) ? c : a;
            float f_ = (le & 2) ? a : c;
            e_ += __shfl_xor_sync(FULL, f_, 2);
            e_ += __shfl_xor_sync(FULL, e_, 4);
            e_ += __shfl_xor_sync(FULL, e_, 8);
            if (le == 0) sA[g][k] = e_;
            else if (le < 4) sB[g][le - 1][k] = e_;
            float sn = c2 * sk - skm1;
            skm1 = sk;
            sk = sn;
        }
    }
    __syncthreads();

    // Phase 2: per (node, s) 20-deep dots, packed over k-pairs
    int s = tid;
    int c = s % 3;
    float phi2 = g_phi[S + s];
    float phi3 = g_phi[2 * S + s];
    float fb2 = filt_b[S + s];
    float fb3 = filt_b[2 * S + s];

    ull w2p[NRBF / 2], w3p[NRBF / 2];
    #pragma unroll
    for (int kk = 0; kk < NRBF / 2; kk++) {
        w2p[kk] = pack2(filt_w[(2 * kk) * 3 * S + S + s],
                        filt_w[(2 * kk + 1) * 3 * S + S + s]);
        w3p[kk] = pack2(filt_w[(2 * kk) * 3 * S + 2 * S + s],
                        filt_w[(2 * kk + 1) * 3 * S + 2 * S + s]);
    }

    for (int ni = 0; ni < NPB; ni++) {
        int nn = blockIdx.x * NPB + ni;
        if (nn >= N) break;
        ull acc2 = 0ull, acc3 = 0ull;
        const ull* pa = (const ull*)&sA[ni][0];
        const ull* pb = (const ull*)&sB[ni][c][0];
        #pragma unroll
        for (int kk = 0; kk < NRBF / 2; kk++) {
            acc2 = ffma2(pa[kk], w2p[kk], acc2);
            acc3 = ffma2(pb[kk], w3p[kk], acc3);
        }
        float a2l, a2h, a3l, a3h;
        unpack2(acc2, a2l, a2h);
        unpack2(acc3, a3l, a3h);
        float ws2 = a2l + a2h + sAb[ni] * fb2;
        float wv  = a3l + a3h + sBb[ni][c] * fb3;
        g_state1[nn * S + s] = phi2 * ws2;
        g_vsum[nn * S + s] = phi3 * wv * sInv[ni];
    }
}

// ---------------------------------------------------------------------------
// Kernel 2: fused per-node MLP, BN=16 nodes/block, transposed smem tiles,
// f32x2 packed FFMA.
// ---------------------------------------------------------------------------
__global__ void __launch_bounds__(128) k_node(
        const float* __restrict__ u_w, const float* __restrict__ v_w,
        const float* __restrict__ w1, const float* __restrict__ b1,
        const float* __restrict__ w2, const float* __restrict__ b2, int N) {
    __shared__ __align__(16) float svT[S][BN];
    __shared__ __align__(16) float ssT[S][BN];
    __shared__ __align__(16) float vnT[S][BN];
    __shared__ __align__(16) float hT[S][BN];
    __shared__ float scp[4][BN];
    __shared__ float sc[BN];

    const unsigned FULL = 0xffffffffu;
    int t = threadIdx.x;
    int n0 = blockIdx.x * BN;

    #pragma unroll
    for (int ni = 0; ni < BN; ni++) {
        int nn = min(n0 + ni, N - 1);
        svT[t][ni] = g_vsum[nn * S + t];
        ssT[t][ni] = g_state1[nn * S + t];
    }
    __syncthreads();

    // uvec, vvec
    ull aU[8], aV[8];
    #pragma unroll
    for (int j = 0; j < 8; j++) { aU[j] = 0ull; aV[j] = 0ull; }
    #pragma unroll 2
    for (int s = 0; s < S; s++) {
        float wu = u_w[s * S + t];
        float wv = v_w[s * S + t];
        ull wuu = pack2(wu, wu), wvv = pack2(wv, wv);
        U4 x0, x1, x2, x3;
        x0.v = *(const float4*)&svT[s][0];
        x1.v = *(const float4*)&svT[s][4];
        x2.v = *(const float4*)&svT[s][8];
        x3.v = *(const float4*)&svT[s][12];
        aU[0] = ffma2(x0.p[0], wuu, aU[0]); aV[0] = ffma2(x0.p[0], wvv, aV[0]);
        aU[1] = ffma2(x0.p[1], wuu, aU[1]); aV[1] = ffma2(x0.p[1], wvv, aV[1]);
        aU[2] = ffma2(x1.p[0], wuu, aU[2]); aV[2] = ffma2(x1.p[0], wvv, aV[2]);
        aU[3] = ffma2(x1.p[1], wuu, aU[3]); aV[3] = ffma2(x1.p[1], wvv, aV[3]);
        aU[4] = ffma2(x2.p[0], wuu, aU[4]); aV[4] = ffma2(x2.p[0], wvv, aV[4]);
        aU[5] = ffma2(x2.p[1], wuu, aU[5]); aV[5] = ffma2(x2.p[1], wvv, aV[5]);
        aU[6] = ffma2(x3.p[0], wuu, aU[6]); aV[6] = ffma2(x3.p[0], wvv, aV[6]);
        aU[7] = ffma2(x3.p[1], wuu, aU[7]); aV[7] = ffma2(x3.p[1], wvv, aV[7]);
    }

    // c[n] partial products + Vnorm (transposed store)
    const float SQ3 = 1.7320508075688772f;
    float prod[BN];
    #pragma unroll
    for (int j = 0; j < 8; j++) {
        float u0, u1, v0, v1;
        unpack2(aU[j], u0, u1);
        unpack2(aV[j], v0, v1);
        prod[2 * j] = u0 * v0;
        prod[2 * j + 1] = u1 * v1;
        vnT[t][2 * j] = SQ3 * fabsf(v0);
        vnT[t][2 * j + 1] = SQ3 * fabsf(v1);
    }
    int warp = t >> 5, lane = t & 31;
    #pragma unroll
    for (int ni = 0; ni < BN; ni++) {
        float v = prod[ni];
        #pragma unroll
        for (int m = 16; m; m >>= 1) v += __shfl_xor_sync(FULL, v, m);
        if (lane == 0) scp[warp][ni] = v;
    }
    __syncthreads();
    if (t < BN) sc[t] = scp[0][t] + scp[1][t] + scp[2][t] + scp[3][t];
    __syncthreads();

    // h = silu([Vnorm, state1] @ upd_w1 + b1)
    ull aH[8];
    #pragma unroll
    for (int j = 0; j < 8; j++) aH[j] = 0ull;
    #pragma unroll 2
    for (int s = 0; s < S; s++) {
        float wA = w1[s * S + t];
        float wB = w1[(S + s) * S + t];
        ull wAA = pack2(wA, wA), wBB = pack2(wB, wB);
        U4 x0, x1, x2, x3, y0, y1, y2, y3;
        x0.v = *(const float4*)&vnT[s][0];
        x1.v = *(const float4*)&vnT[s][4];
        x2.v = *(const float4*)&vnT[s][8];
        x3.v = *(const float4*)&vnT[s][12];
        y0.v = *(const float4*)&ssT[s][0];
        y1.v = *(const float4*)&ssT[s][4];
        y2.v = *(const float4*)&ssT[s][8];
        y3.v = *(const float4*)&ssT[s][12];
        aH[0] = ffma2(x0.p[0], wAA, aH[0]); aH[0] = ffma2(y0.p[0], wBB, aH[0]);
        aH[1] = ffma2(x0.p[1], wAA, aH[1]); aH[1] = ffma2(y0.p[1], wBB, aH[1]);
        aH[2] = ffma2(x1.p[0], wAA, aH[2]); aH[2] = ffma2(y1.p[0], wBB, aH[2]);
        aH[3] = ffma2(x1.p[1], wAA, aH[3]); aH[3] = ffma2(y1.p[1], wBB, aH[3]);
        aH[4] = ffma2(x2.p[0], wAA, aH[4]); aH[4] = ffma2(y2.p[0], wBB, aH[4]);
        aH[5] = ffma2(x2.p[1], wAA, aH[5]); aH[5] = ffma2(y2.p[1], wBB, aH[5]);
        aH[6] = ffma2(x3.p[0], wAA, aH[6]); aH[6] = ffma2(y3.p[0], wBB, aH[6]);
        aH[7] = ffma2(x3.p[1], wAA, aH[7]); aH[7] = ffma2(y3.p[1], wBB, aH[7]);
    }
    float bb = b1[t];
    #pragma unroll
    for (int j = 0; j < 8; j++) {
        float h0, h1;
        unpack2(aH[j], h0, h1);
        hT[t][2 * j] = siluf(h0 + bb);
        hT[t][2 * j + 1] = siluf(h1 + bb);
    }
    __syncthreads();

    // asv, ass = h @ upd_w2 slices
    ull aSV[8], aSS[8];
    #pragma unroll
    for (int j = 0; j < 8; j++) { aSV[j] = 0ull; aSS[j] = 0ull; }
    #pragma unroll 2
    for (int s = 0; s < S; s++) {
        float wsv = w2[s * 3 * S + S + t];
        float wss = w2[s * 3 * S + 2 * S + t];
        ull wv2 = pack2(wsv, wsv), ws2 = pack2(wss, wss);
        U4 x0, x1, x2, x3;
        x0.v = *(const float4*)&hT[s][0];
        x1.v = *(const float4*)&hT[s][4];
        x2.v = *(const float4*)&hT[s][8];
        x3.v = *(const float4*)&hT[s][12];
        aSV[0] = ffma2(x0.p[0], wv2, aSV[0]); aSS[0] = ffma2(x0.p[0], ws2, aSS[0]);
        aSV[1] = ffma2(x0.p[1], wv2, aSV[1]); aSS[1] = ffma2(x0.p[1], ws2, aSS[1]);
        aSV[2] = ffma2(x1.p[0], wv2, aSV[2]); aSS[2] = ffma2(x1.p[0], ws2, aSS[2]);
        aSV[3] = ffma2(x1.p[1], wv2, aSV[3]); aSS[3] = ffma2(x1.p[1], ws2, aSS[3]);
        aSV[4] = ffma2(x2.p[0], wv2, aSV[4]); aSS[4] = ffma2(x2.p[0], ws2, aSS[4]);
        aSV[5] = ffma2(x2.p[1], wv2, aSV[5]); aSS[5] = ffma2(x2.p[1], ws2, aSS[5]);
        aSV[6] = ffma2(x3.p[0], wv2, aSV[6]); aSS[6] = ffma2(x3.p[0], ws2, aSS[6]);
        aSV[7] = ffma2(x3.p[1], wv2, aSV[7]); aSS[7] = ffma2(x3.p[1], ws2, aSS[7]);
    }
    float bsv = b2[S + t];
    float bss = b2[2 * S + t];
    #pragma unroll
    for (int j = 0; j < 8; j++) {
        float sv0, sv1, ss0, ss1;
        unpack2(aSV[j], sv0, sv1);
        unpack2(aSS[j], ss0, ss1);
        int nn0 = n0 + 2 * j;
        if (nn0 < N)
            g_statef[nn0 * S + t] = (ss0 + bss) + 3.0f * sc[2 * j] * (sv0 + bsv);
        if (nn0 + 1 < N)
            g_statef[(nn0 + 1) * S + t] = (ss1 + bss) + 3.0f * sc[2 * j + 1] * (sv1 + bsv);
    }
}

// ---------------------------------------------------------------------------
// Kernel 3: graph segment-sum via per-block shared accumulator (deterministic)
// ---------------------------------------------------------------------------
__global__ void __launch_bounds__(128) k_gp(const int* __restrict__ gidx,
                                            int N, int G) {
    __shared__ float acc[GMAX][S];
    int t = threadIdx.x;
    for (int g = 0; g < G; g++) acc[g][t] = 0.0f;  // thread t owns column t
    int per = (N + GP_BLOCKS - 1) / GP_BLOCKS;
    int n0 = blockIdx.x * per;
    int n1 = min(n0 + per, N);
    #pragma unroll 4
    for (int n = n0; n < n1; n++) {
        int g = __ldg(&gidx[n]);
        acc[g][t] += g_statef[n * S + t];
    }
    for (int g = 0; g < G; g++)
        g_partial[(blockIdx.x * G + g) * S + t] = acc[g][t];
}

// ---------------------------------------------------------------------------
// Kernel 4: combine partials + output MLP per graph
// ---------------------------------------------------------------------------
__global__ void k_out(const float* __restrict__ w1, const float* __restrict__ b1,
                      const float* __restrict__ w2, const float* __restrict__ b2,
                      float* __restrict__ out, int G) {
    __shared__ float gs[S];
    __shared__ float red[4];
    int g = blockIdx.x, t = threadIdx.x;
    float acc = 0.0f;
    #pragma unroll 4
    for (int ch = 0; ch < GP_BLOCKS; ch++)
        acc += g_partial[(ch * G + g) * S + t];
    gs[t] = acc;
    __syncthreads();
    float hacc = b1[t];
    #pragma unroll 4
    for (int s = 0; s < S; s++) hacc += gs[s] * w1[s * S + t];
    float h = hacc / (1.0f + expf(-hacc));
    float p = h * w2[t];
    #pragma unroll
    for (int m = 16; m; m >>= 1) p += __shfl_xor_sync(0xffffffffu, p, m);
    int warp = t >> 5, lane = t & 31;
    if (lane == 0) red[warp] = p;
    __syncthreads();
    if (t == 0) out[g] = red[0] + red[1] + red[2] + red[3] + b2[0];
}

// ---------------------------------------------------------------------------
extern "C" void kernel_launch(void* const* d_in, const int* in_sizes, int n_in,
                              void* d_out, int out_size) {
    int N = in_sizes[3];                 // node_graph_index
    int off = (n_in >= 22) ? 1 : 0;      // num_graphs scalar present?

    const float* diffs   = (const float*)d_in[0];
    const float* lens    = (const float*)d_in[1];
    const int*   gidx    = (const int*)d_in[3];
    const float* emb0    = (const float*)d_in[4 + off];
    const float* phi_w1  = (const float*)d_in[5 + off];
    const float* phi_b1  = (const float*)d_in[6 + off];
    const float* phi_w2  = (const float*)d_in[7 + off];
    const float* phi_b2  = (const float*)d_in[8 + off];
    const float* filt_w  = (const float*)d_in[9 + off];
    const float* filt_b  = (const float*)d_in[10 + off];
    const float* u_w     = (const float*)d_in[11 + off];
    const float* v_w     = (const float*)d_in[12 + off];
    const float* upd_w1  = (const float*)d_in[13 + off];
    const float* upd_b1  = (const float*)d_in[14 + off];
    const float* upd_w2  = (const float*)d_in[15 + off];
    const float* upd_b2  = (const float*)d_in[16 + off];
    const float* out_w1  = (const float*)d_in[17 + off];
    const float* out_b1  = (const float*)d_in[18 + off];
    const float* out_w2  = (const float*)d_in[19 + off];
    const float* out_b2  = (const float*)d_in[20 + off];
    float* out = (float*)d_out;
    int G = out_size;

    k_phi<<<1, 3 * S>>>(emb0, phi_w1, phi_b1, phi_w2, phi_b2);

    int nblk1 = (N + NPB - 1) / NPB;
    k_edge<<<nblk1, 128>>>(diffs, lens, filt_w, filt_b, N);

    int nblk2 = (N + BN - 1) / BN;
    k_node<<<nblk2, 128>>>(u_w, v_w, upd_w1, upd_b1, upd_w2, upd_b2, N);

    k_gp<<<GP_BLOCKS, 128>>>(gidx, N, G);

    k_out<<<G, 128>>>(out_w1, out_b1, out_w2, out_b2, out, G);
}